// round 4
// baseline (speedup 1.0000x reference)
#include <cuda_runtime.h>
#include <cuda_bf16.h>
#include <cstdint>

// Segment-mean readout:
//   out[g, :] = mean(atom_hiddens[start_g : start_g+size_g, :])   (0 if size_g == 0)
// atom_hiddens: [N_ATOMS, D] float32       (1M x 300)
// a_scope:      [N_GRAPHS, 2] int32        (start, size)
//
// HBM-roofline streaming: 1.2 GB read + 60 MB write, zero reuse.
// R4: 2 adjacent float4 chunks per thread -> 1024B contiguous per warp per row,
// half the threads (halves scope-read traffic), unroll-4 -> 8 LDG.128 in flight.

__global__ void readout_mean_v4p(const float4* __restrict__ A,
                                 const int* __restrict__ scope,
                                 float4* __restrict__ out,
                                 int n_graphs, int chunks, int npairs, int n_atoms)
{
    int total = n_graphs * npairs;                     // 1.9M, fits int32
    int t = blockIdx.x * blockDim.x + threadIdx.x;
    if (t >= total) return;

    int g = t / npairs;
    int j = t - g * npairs;
    int c0 = 2 * j;
    bool has_c1 = (c0 + 1) < chunks;

    int start = scope[2 * g];
    int size  = scope[2 * g + 1];

    // Defensive clamp to [0, n_atoms)
    if (start < 0) start = 0;
    int end = start + size;
    if (end > n_atoms) end = n_atoms;
    int cnt = end - start;
    if (cnt < 0) cnt = 0;

    const float4* p = A + start * chunks + c0;         // <= 75M elems, fits int32

    float4 a0 = make_float4(0.f, 0.f, 0.f, 0.f);
    float4 a1 = make_float4(0.f, 0.f, 0.f, 0.f);
    int i = 0;
    if (has_c1) {
        // 8 independent streaming LDG.128 per iteration; cnt=20 -> 5 iterations
        for (; i + 4 <= cnt; i += 4) {
            const float4* q = p + i * chunks;
            float4 u0 = __ldcs(q);
            float4 w0 = __ldcs(q + 1);
            float4 u1 = __ldcs(q + chunks);
            float4 w1 = __ldcs(q + chunks + 1);
            float4 u2 = __ldcs(q + 2 * chunks);
            float4 w2 = __ldcs(q + 2 * chunks + 1);
            float4 u3 = __ldcs(q + 3 * chunks);
            float4 w3 = __ldcs(q + 3 * chunks + 1);
            a0.x += (u0.x + u1.x) + (u2.x + u3.x);
            a0.y += (u0.y + u1.y) + (u2.y + u3.y);
            a0.z += (u0.z + u1.z) + (u2.z + u3.z);
            a0.w += (u0.w + u1.w) + (u2.w + u3.w);
            a1.x += (w0.x + w1.x) + (w2.x + w3.x);
            a1.y += (w0.y + w1.y) + (w2.y + w3.y);
            a1.z += (w0.z + w1.z) + (w2.z + w3.z);
            a1.w += (w0.w + w1.w) + (w2.w + w3.w);
        }
        for (; i < cnt; ++i) {
            const float4* q = p + i * chunks;
            float4 u = __ldcs(q);
            float4 w = __ldcs(q + 1);
            a0.x += u.x; a0.y += u.y; a0.z += u.z; a0.w += u.w;
            a1.x += w.x; a1.y += w.y; a1.z += w.z; a1.w += w.w;
        }
    } else {
        // tail chunk (c0 == chunks-1 when chunks is odd)
        for (; i + 4 <= cnt; i += 4) {
            const float4* q = p + i * chunks;
            float4 u0 = __ldcs(q);
            float4 u1 = __ldcs(q + chunks);
            float4 u2 = __ldcs(q + 2 * chunks);
            float4 u3 = __ldcs(q + 3 * chunks);
            a0.x += (u0.x + u1.x) + (u2.x + u3.x);
            a0.y += (u0.y + u1.y) + (u2.y + u3.y);
            a0.z += (u0.z + u1.z) + (u2.z + u3.z);
            a0.w += (u0.w + u1.w) + (u2.w + u3.w);
        }
        for (; i < cnt; ++i) {
            float4 u = __ldcs(p + i * chunks);
            a0.x += u.x; a0.y += u.y; a0.z += u.z; a0.w += u.w;
        }
    }

    // Reference semantics: divide by max(size,1); size==0 -> zeros
    float inv = (size > 0) ? (1.0f / (float)size) : 0.0f;
    a0.x *= inv; a0.y *= inv; a0.z *= inv; a0.w *= inv;

    float4* o = out + g * chunks + c0;
    __stcs(o, a0);
    if (has_c1) {
        a1.x *= inv; a1.y *= inv; a1.z *= inv; a1.w *= inv;
        __stcs(o + 1, a1);
    }
}

// Scalar fallback for D % 4 != 0
__global__ void readout_mean_scalar(const float* __restrict__ A,
                                    const int* __restrict__ scope,
                                    float* __restrict__ out,
                                    int n_graphs, int D, int n_atoms)
{
    long long total = (long long)n_graphs * D;
    long long t = (long long)blockIdx.x * blockDim.x + threadIdx.x;
    if (t >= total) return;

    int g = (int)(t / D);
    int d = (int)(t - (long long)g * D);

    int start = scope[2 * g];
    int size  = scope[2 * g + 1];

    if (start < 0) start = 0;
    int end = start + size;
    if (end > n_atoms) end = n_atoms;
    int cnt = end - start;
    if (cnt < 0) cnt = 0;

    const float* p = A + (long long)start * D + d;
    float acc = 0.f;
    for (int i = 0; i < cnt; ++i)
        acc += __ldcs(p + (long long)i * D);

    float inv = (size > 0) ? (1.0f / (float)size) : 0.0f;
    out[(long long)g * D + d] = acc * inv;
}

extern "C" void kernel_launch(void* const* d_in, const int* in_sizes, int n_in,
                              void* d_out, int out_size)
{
    const float* atom_hiddens = (const float*)d_in[0];
    const int*   a_scope      = (const int*)d_in[1];

    int n_graphs = in_sizes[1] / 2;
    int D = out_size / n_graphs;              // 300
    int n_atoms = (int)((long long)in_sizes[0] / D);

    if ((D & 3) == 0) {
        int chunks = D / 4;                   // 75
        int npairs = (chunks + 1) / 2;        // 38
        long long total = (long long)n_graphs * npairs;
        int threads = 256;
        int blocks = (int)((total + threads - 1) / threads);
        readout_mean_v4p<<<blocks, threads>>>(
            (const float4*)atom_hiddens, a_scope, (float4*)d_out,
            n_graphs, chunks, npairs, n_atoms);
    } else {
        long long total = (long long)n_graphs * D;
        int threads = 256;
        int blocks = (int)((total + threads - 1) / threads);
        readout_mean_scalar<<<blocks, threads>>>(
            atom_hiddens, a_scope, (float*)d_out, n_graphs, D, n_atoms);
    }
}

// round 5
// speedup vs baseline: 1.0763x; 1.0763x over previous
#include <cuda_runtime.h>
#include <cuda_bf16.h>
#include <cstdint>

// Segment-mean readout:
//   out[g, :] = mean(atom_hiddens[start_g : start_g+size_g, :])   (0 if size_g == 0)
// atom_hiddens: [N_ATOMS, D] float32       (1M x 300)
// a_scope:      [N_GRAPHS, 2] int32        (start, size)
//
// HBM-roofline streaming: 1.2 GB read + 60 MB write, zero reuse.
// R5 = R3 layout (the fast one): one float4 chunk per thread, lane-contiguous
// LDG.128 per instruction, unroll-5 (cnt=20 -> 4 iterations, no tail),
// streaming cache hints, int32 indexing. Block=512.

__global__ void readout_mean_v4(const float4* __restrict__ A,
                                const int* __restrict__ scope,
                                float4* __restrict__ out,
                                int n_graphs, int chunks, int n_atoms)
{
    int total = n_graphs * chunks;                       // 3.75M, fits int32
    int t = blockIdx.x * blockDim.x + threadIdx.x;
    if (t >= total) return;

    int g = t / chunks;
    int c = t - g * chunks;

    int start = __ldg(scope + 2 * g);
    int size  = __ldg(scope + 2 * g + 1);

    // Defensive clamp to [0, n_atoms)
    if (start < 0) start = 0;
    int end = start + size;
    if (end > n_atoms) end = n_atoms;
    int cnt = end - start;
    if (cnt < 0) cnt = 0;

    const float4* p = A + start * chunks + c;            // <= 75M elems, fits int32

    float4 acc = make_float4(0.f, 0.f, 0.f, 0.f);
    int i = 0;
    // 5 independent streaming LDG.128 per iteration; cnt=20 -> 4 iterations, no tail
    for (; i + 5 <= cnt; i += 5) {
        const float4* q = p + i * chunks;
        float4 v0 = __ldcs(q);
        float4 v1 = __ldcs(q + chunks);
        float4 v2 = __ldcs(q + 2 * chunks);
        float4 v3 = __ldcs(q + 3 * chunks);
        float4 v4 = __ldcs(q + 4 * chunks);
        acc.x += (v0.x + v1.x) + (v2.x + v3.x) + v4.x;
        acc.y += (v0.y + v1.y) + (v2.y + v3.y) + v4.y;
        acc.z += (v0.z + v1.z) + (v2.z + v3.z) + v4.z;
        acc.w += (v0.w + v1.w) + (v2.w + v3.w) + v4.w;
    }
    for (; i < cnt; ++i) {
        float4 v = __ldcs(p + i * chunks);
        acc.x += v.x; acc.y += v.y; acc.z += v.z; acc.w += v.w;
    }

    // Reference semantics: divide by max(size,1); size==0 -> zeros (acc already 0)
    float inv = (size > 0) ? (1.0f / (float)size) : 0.0f;
    acc.x *= inv; acc.y *= inv; acc.z *= inv; acc.w *= inv;

    __stcs(out + g * chunks + c, acc);
}

// Scalar fallback for D % 4 != 0
__global__ void readout_mean_scalar(const float* __restrict__ A,
                                    const int* __restrict__ scope,
                                    float* __restrict__ out,
                                    int n_graphs, int D, int n_atoms)
{
    long long total = (long long)n_graphs * D;
    long long t = (long long)blockIdx.x * blockDim.x + threadIdx.x;
    if (t >= total) return;

    int g = (int)(t / D);
    int d = (int)(t - (long long)g * D);

    int start = scope[2 * g];
    int size  = scope[2 * g + 1];

    if (start < 0) start = 0;
    int end = start + size;
    if (end > n_atoms) end = n_atoms;
    int cnt = end - start;
    if (cnt < 0) cnt = 0;

    const float* p = A + (long long)start * D + d;
    float acc = 0.f;
    for (int i = 0; i < cnt; ++i)
        acc += __ldcs(p + (long long)i * D);

    float inv = (size > 0) ? (1.0f / (float)size) : 0.0f;
    out[(long long)g * D + d] = acc * inv;
}

extern "C" void kernel_launch(void* const* d_in, const int* in_sizes, int n_in,
                              void* d_out, int out_size)
{
    const float* atom_hiddens = (const float*)d_in[0];
    const int*   a_scope      = (const int*)d_in[1];

    int n_graphs = in_sizes[1] / 2;
    int D = out_size / n_graphs;              // 300
    int n_atoms = (int)((long long)in_sizes[0] / D);

    if ((D & 3) == 0) {
        int chunks = D / 4;                   // 75
        long long total = (long long)n_graphs * chunks;
        int threads = 512;
        int blocks = (int)((total + threads - 1) / threads);
        readout_mean_v4<<<blocks, threads>>>(
            (const float4*)atom_hiddens, a_scope, (float4*)d_out,
            n_graphs, chunks, n_atoms);
    } else {
        long long total = (long long)n_graphs * D;
        int threads = 256;
        int blocks = (int)((total + threads - 1) / threads);
        readout_mean_scalar<<<blocks, threads>>>(
            atom_hiddens, a_scope, (float*)d_out, n_graphs, D, n_atoms);
    }
}

// round 7
// speedup vs baseline: 1.1136x; 1.0347x over previous
#include <cuda_runtime.h>
#include <cuda_bf16.h>
#include <cstdint>

// Segment-mean readout:
//   out[g, :] = mean(atom_hiddens[start_g : start_g+size_g, :])   (0 if size_g == 0)
// atom_hiddens: [N_ATOMS, D] float32       (1M x 300)
// a_scope:      [N_GRAPHS, 2] int32        (start, size)
//
// HBM-roofline streaming: 1.2 GB read + 60 MB write, zero reuse.
// R6 = R3 config (block=256, one float4 chunk/thread, lane-contiguous LDG.128,
// unroll-5, streaming hints, int32 indexing) + __launch_bounds__(256,6) to cap
// regs at 42 -> 6 blocks/SM resident (occ 57% -> ~70%).

__global__ void __launch_bounds__(256, 6)
readout_mean_v4(const float4* __restrict__ A,
                const int* __restrict__ scope,
                float4* __restrict__ out,
                int n_graphs, int chunks, int n_atoms)
{
    int total = n_graphs * chunks;                       // 3.75M, fits int32
    int t = blockIdx.x * blockDim.x + threadIdx.x;
    if (t >= total) return;

    int g = t / chunks;
    int c = t - g * chunks;

    int start = __ldg(scope + 2 * g);
    int size  = __ldg(scope + 2 * g + 1);

    // Defensive clamp to [0, n_atoms)
    if (start < 0) start = 0;
    int end = start + size;
    if (end > n_atoms) end = n_atoms;
    int cnt = end - start;
    if (cnt < 0) cnt = 0;

    const float4* p = A + start * chunks + c;            // <= 75M elems, fits int32

    float4 acc = make_float4(0.f, 0.f, 0.f, 0.f);
    int i = 0;
    // 5 independent streaming LDG.128 per iteration; cnt=20 -> 4 iterations, no tail
    for (; i + 5 <= cnt; i += 5) {
        const float4* q = p + i * chunks;
        float4 v0 = __ldcs(q);
        float4 v1 = __ldcs(q + chunks);
        float4 v2 = __ldcs(q + 2 * chunks);
        float4 v3 = __ldcs(q + 3 * chunks);
        float4 v4 = __ldcs(q + 4 * chunks);
        acc.x += (v0.x + v1.x) + (v2.x + v3.x) + v4.x;
        acc.y += (v0.y + v1.y) + (v2.y + v3.y) + v4.y;
        acc.z += (v0.z + v1.z) + (v2.z + v3.z) + v4.z;
        acc.w += (v0.w + v1.w) + (v2.w + v3.w) + v4.w;
    }
    for (; i < cnt; ++i) {
        float4 v = __ldcs(p + i * chunks);
        acc.x += v.x; acc.y += v.y; acc.z += v.z; acc.w += v.w;
    }

    // Reference semantics: divide by max(size,1); size==0 -> zeros (acc already 0)
    float inv = (size > 0) ? (1.0f / (float)size) : 0.0f;
    acc.x *= inv; acc.y *= inv; acc.z *= inv; acc.w *= inv;

    __stcs(out + g * chunks + c, acc);
}

// Scalar fallback for D % 4 != 0
__global__ void readout_mean_scalar(const float* __restrict__ A,
                                    const int* __restrict__ scope,
                                    float* __restrict__ out,
                                    int n_graphs, int D, int n_atoms)
{
    long long total = (long long)n_graphs * D;
    long long t = (long long)blockIdx.x * blockDim.x + threadIdx.x;
    if (t >= total) return;

    int g = (int)(t / D);
    int d = (int)(t - (long long)g * D);

    int start = scope[2 * g];
    int size  = scope[2 * g + 1];

    if (start < 0) start = 0;
    int end = start + size;
    if (end > n_atoms) end = n_atoms;
    int cnt = end - start;
    if (cnt < 0) cnt = 0;

    const float* p = A + (long long)start * D + d;
    float acc = 0.f;
    for (int i = 0; i < cnt; ++i)
        acc += __ldcs(p + (long long)i * D);

    float inv = (size > 0) ? (1.0f / (float)size) : 0.0f;
    out[(long long)g * D + d] = acc * inv;
}

extern "C" void kernel_launch(void* const* d_in, const int* in_sizes, int n_in,
                              void* d_out, int out_size)
{
    const float* atom_hiddens = (const float*)d_in[0];
    const int*   a_scope      = (const int*)d_in[1];

    int n_graphs = in_sizes[1] / 2;
    int D = out_size / n_graphs;              // 300
    int n_atoms = (int)((long long)in_sizes[0] / D);

    if ((D & 3) == 0) {
        int chunks = D / 4;                   // 75
        long long total = (long long)n_graphs * chunks;
        int threads = 256;
        int blocks = (int)((total + threads - 1) / threads);
        readout_mean_v4<<<blocks, threads>>>(
            (const float4*)atom_hiddens, a_scope, (float4*)d_out,
            n_graphs, chunks, n_atoms);
    } else {
        long long total = (long long)n_graphs * D;
        int threads = 256;
        int blocks = (int)((total + threads - 1) / threads);
        readout_mean_scalar<<<blocks, threads>>>(
            atom_hiddens, a_scope, (float*)d_out, n_graphs, D, n_atoms);
    }
}

// round 9
// speedup vs baseline: 1.1144x; 1.0007x over previous
#include <cuda_runtime.h>
#include <cuda_bf16.h>
#include <cstdint>

// Segment-mean readout:
//   out[g, :] = mean(atom_hiddens[start_g : start_g+size_g, :])   (0 if size_g == 0)
// atom_hiddens: [N_ATOMS, D] float32       (1M x 300)
// a_scope:      [N_GRAPHS, 2] int32        (start, size)
//
// HBM-roofline streaming: 1.2 GB read + 60 MB write, zero reuse.
// Converged config (R3/R6 winner): block=256, one float4 chunk per thread,
// lane-contiguous LDG.128 per instruction, unroll-5 (cnt=20 -> 4 iterations,
// no tail), streaming cache hints, int32 indexing, launch_bounds(256,6)
// (regs<=40, 6 blocks/SM). Measured 86% of HBM spec -- practical ceiling for
// a 95%-read stream; restructures beyond this shape regressed (R4, R5).

__global__ void __launch_bounds__(256, 6)
readout_mean_v4(const float4* __restrict__ A,
                const int* __restrict__ scope,
                float4* __restrict__ out,
                int n_graphs, int chunks, int n_atoms)
{
    int total = n_graphs * chunks;                       // 3.75M, fits int32
    int t = blockIdx.x * blockDim.x + threadIdx.x;
    if (t >= total) return;

    int g = t / chunks;
    int c = t - g * chunks;

    int start = __ldg(scope + 2 * g);
    int size  = __ldg(scope + 2 * g + 1);

    // Branch-free clamp to [0, n_atoms)
    start = max(start, 0);
    int cnt = min(start + size, n_atoms) - start;
    cnt = max(cnt, 0);

    const float4* p = A + start * chunks + c;            // <= 75M elems, fits int32

    float4 acc = make_float4(0.f, 0.f, 0.f, 0.f);
    int i = 0;
    // 5 independent streaming LDG.128 per iteration; cnt=20 -> 4 iterations, no tail
    for (; i + 5 <= cnt; i += 5) {
        const float4* q = p + i * chunks;
        float4 v0 = __ldcs(q);
        float4 v1 = __ldcs(q + chunks);
        float4 v2 = __ldcs(q + 2 * chunks);
        float4 v3 = __ldcs(q + 3 * chunks);
        float4 v4 = __ldcs(q + 4 * chunks);
        acc.x += (v0.x + v1.x) + (v2.x + v3.x) + v4.x;
        acc.y += (v0.y + v1.y) + (v2.y + v3.y) + v4.y;
        acc.z += (v0.z + v1.z) + (v2.z + v3.z) + v4.z;
        acc.w += (v0.w + v1.w) + (v2.w + v3.w) + v4.w;
    }
    for (; i < cnt; ++i) {
        float4 v = __ldcs(p + i * chunks);
        acc.x += v.x; acc.y += v.y; acc.z += v.z; acc.w += v.w;
    }

    // Reference semantics: divide by max(size,1); size==0 -> zeros (acc already 0)
    float inv = (size > 0) ? (1.0f / (float)size) : 0.0f;
    acc.x *= inv; acc.y *= inv; acc.z *= inv; acc.w *= inv;

    __stcs(out + g * chunks + c, acc);
}

// Scalar fallback for D % 4 != 0
__global__ void readout_mean_scalar(const float* __restrict__ A,
                                    const int* __restrict__ scope,
                                    float* __restrict__ out,
                                    int n_graphs, int D, int n_atoms)
{
    long long total = (long long)n_graphs * D;
    long long t = (long long)blockIdx.x * blockDim.x + threadIdx.x;
    if (t >= total) return;

    int g = (int)(t / D);
    int d = (int)(t - (long long)g * D);

    int start = scope[2 * g];
    int size  = scope[2 * g + 1];

    start = max(start, 0);
    int cnt = min(start + size, n_atoms) - start;
    cnt = max(cnt, 0);

    const float* p = A + (long long)start * D + d;
    float acc = 0.f;
    for (int i = 0; i < cnt; ++i)
        acc += __ldcs(p + (long long)i * D);

    float inv = (size > 0) ? (1.0f / (float)size) : 0.0f;
    out[(long long)g * D + d] = acc * inv;
}

extern "C" void kernel_launch(void* const* d_in, const int* in_sizes, int n_in,
                              void* d_out, int out_size)
{
    const float* atom_hiddens = (const float*)d_in[0];
    const int*   a_scope      = (const int*)d_in[1];

    int n_graphs = in_sizes[1] / 2;
    int D = out_size / n_graphs;              // 300
    int n_atoms = (int)((long long)in_sizes[0] / D);

    if ((D & 3) == 0) {
        int chunks = D / 4;                   // 75
        long long total = (long long)n_graphs * chunks;
        int threads = 256;
        int blocks = (int)((total + threads - 1) / threads);
        readout_mean_v4<<<blocks, threads>>>(
            (const float4*)atom_hiddens, a_scope, (float4*)d_out,
            n_graphs, chunks, n_atoms);
    } else {
        long long total = (long long)n_graphs * D;
        int threads = 256;
        int blocks = (int)((total + threads - 1) / threads);
        readout_mean_scalar<<<blocks, threads>>>(
            atom_hiddens, a_scope, (float*)d_out, n_graphs, D, n_atoms);
    }
}